// round 17
// baseline (speedup 1.0000x reference)
#include <cuda_runtime.h>
#include <cuda_bf16.h>

// Circular self-convolution via half-length real FFT (radix-4), one row per
// CTA. 384 CTAs x 128 threads (R13/R16 skeleton).
//
// R17 = R16 + twiddle hoisting:
//  - ALL per-stage twiddles (stages 512/128/32, both middle w's) computed
//    ONCE in the prologue, in registers, inside the gmem-load latency
//    shadow; fwd, inv, and epilogue reuse the same registers (bit-identical
//    -> exact unwind, rel_err must not change).
//  - Stage-8 twiddles are compile-time constants (pos in {0,1}): selects
//    instead of a MUFU chain.
// Everything else identical to R16.

#define N_CONV 1024
#define HF 512
#define THREADS 128

#define P2(i) ((i) + ((i) >> 4))
#define SQH 0.70710678118654752f

// Position of frequency k after stages r4(512),r4(128),r4(32),r4(8),r2(2).
__device__ __forceinline__ int rev_inv(int k) {
    return ((k & 3) << 7) | (((k >> 2) & 3) << 5) | (((k >> 4) & 3) << 3)
         | (((k >> 6) & 3) << 1) | ((k >> 8) & 1);
}

__device__ __forceinline__ float fsin(float x) {
    float r; asm("sin.approx.f32 %0, %1;" : "=f"(r) : "f"(x)); return r;
}
__device__ __forceinline__ float fcos(float x) {
    float r; asm("cos.approx.f32 %0, %1;" : "=f"(r) : "f"(x)); return r;
}

__device__ __forceinline__ float2 cadd(float2 a, float2 b) { return make_float2(a.x + b.x, a.y + b.y); }
__device__ __forceinline__ float2 csub(float2 a, float2 b) { return make_float2(a.x - b.x, a.y - b.y); }
__device__ __forceinline__ float2 cmul(float2 a, float2 w) {
    return make_float2(a.x * w.x - a.y * w.y, a.x * w.y + a.y * w.x);
}
__device__ __forceinline__ float2 cmulc(float2 a, float2 w) {   // a * conj(w)
    return make_float2(a.x * w.x + a.y * w.y, a.y * w.x - a.x * w.y);
}
__device__ __forceinline__ float2 submuli(float2 a, float2 b) {  // a - i*b
    return make_float2(a.x + b.y, a.y - b.x);
}
__device__ __forceinline__ float2 addmuli(float2 a, float2 b) {  // a + i*b
    return make_float2(a.x - b.y, a.y + b.x);
}
__device__ __forceinline__ float2 csq(float2 a) {
    return make_float2(a.x * a.x - a.y * a.y, 2.0f * a.x * a.y);
}

// w1 = e^{-i th}, w2 = w1^2, w3 = w1^3.  (th < pi/2 at every call site)
__device__ __forceinline__ void tw3(float th, float2& w1, float2& w2, float2& w3)
{
    w1 = make_float2(fcos(th), -fsin(th));
    w2 = cmul(w1, w1);
    w3 = cmul(w1, w2);
}

// Forward DIF radix-4 stage, in-place, twiddles passed in.
template<int L>
__device__ __forceinline__ void fwd_stage(float2* X, int t,
                                          float2 w1, float2 w2, float2 w3)
{
    const int q    = L >> 2;
    const int blk  = t / q;
    const int pos  = t % q;
    const int base = blk * L + pos;
    const int i0 = P2(base), i1 = P2(base + q), i2 = P2(base + 2*q), i3 = P2(base + 3*q);

    const float2 a0 = X[i0], a1 = X[i1], a2 = X[i2], a3 = X[i3];
    const float2 t0 = cadd(a0, a2);
    const float2 t1 = csub(a0, a2);
    const float2 t2 = cadd(a1, a3);
    const float2 t3 = csub(a1, a3);
    X[i0] = cadd(t0, t2);
    X[i1] = cmul(submuli(t1, t3), w1);
    X[i2] = cmul(csub(t0, t2), w2);
    X[i3] = cmul(addmuli(t1, t3), w3);
}

// Inverse radix-4 stage (un-twiddle by conj, inverse butterfly).
template<int L>
__device__ __forceinline__ void inv_stage(float2* X, int t,
                                          float2 w1, float2 w2, float2 w3)
{
    const int q    = L >> 2;
    const int blk  = t / q;
    const int pos  = t % q;
    const int base = blk * L + pos;
    const int i0 = P2(base), i1 = P2(base + q), i2 = P2(base + 2*q), i3 = P2(base + 3*q);

    const float2 a0 = X[i0];
    const float2 a1 = cmulc(X[i1], w1);
    const float2 a2 = cmulc(X[i2], w2);
    const float2 a3 = cmulc(X[i3], w3);
    const float2 t0 = cadd(a0, a2);
    const float2 t1 = csub(a0, a2);
    const float2 t2 = cadd(a1, a3);
    const float2 t3 = csub(a1, a3);
    X[i0] = cadd(t0, t2);
    X[i1] = addmuli(t1, t3);
    X[i2] = csub(t0, t2);
    X[i3] = submuli(t1, t3);
}

// Radix-2 stage L=2 (thread-local pairs; same butterfly fwd and inv).
__device__ __forceinline__ void r2_stage(float2* X, int t)
{
    const int b = 4 * t;
    const int i0 = P2(b), i1 = P2(b + 1), i2 = P2(b + 2), i3 = P2(b + 3);
    const float2 a0 = X[i0], a1 = X[i1], a2 = X[i2], a3 = X[i3];
    X[i0] = cadd(a0, a1);
    X[i1] = csub(a0, a1);
    X[i2] = cadd(a2, a3);
    X[i3] = csub(a2, a3);
}

// Middle unit for pair (k, 512-k): rfft combine + square + inverse-pack.
// w = W1024^k passed in (precomputed). 1/512 folded into QS.
__device__ __forceinline__ void middle_unit(float2* X, int k, float2 w)
{
    const int pk = P2(rev_inv(k));
    const int pm = P2(rev_inv((HF - k) & (HF - 1)));

    const float2 Uk = X[pk];
    const float2 Um = X[pm];

    const float2 E = make_float2(0.5f * (Uk.x + Um.x), 0.5f * (Uk.y - Um.y));
    const float2 O = make_float2(0.5f * (Uk.y + Um.y), 0.5f * (Um.x - Uk.x));

    const float2 wO = cmul(O, w);
    const float2 Xp = cadd(E, wO);             // X[k]
    const float2 Xm = csub(E, wO);             // X[k+512]

    const float2 P = csq(Xp);
    const float2 M = csq(Xm);
    const float QS = 9.765625e-4f;             // 0.5 * (1/512)
    const float2 S  = make_float2(QS * (P.x + M.x), QS * (P.y + M.y));
    const float2 Dm = make_float2(QS * (P.x - M.x), QS * (P.y - M.y));

    const float2 r = cmulc(Dm, w);             // conj(w)*Dm
    const float2 Vk = make_float2(S.x - r.y, S.y + r.x);     // S + i*r

    const float2 q2 = cmul(make_float2(Dm.x, -Dm.y), w);     // w*conj(Dm)
    const float2 Vm = make_float2(S.x - q2.y, -S.y + q2.x);  // conj(S)+i*q2

    X[pk] = Vk;
    X[pm] = Vm;
}

__global__ __launch_bounds__(THREADS, 3)
void mcf_r17_kernel(const float* __restrict__ x1,
                    const float* __restrict__ x2,
                    const float* __restrict__ x3,
                    float* __restrict__ out)
{
    __shared__ __align__(16) float2 X[546];     // 512 + padding

    const int bx  = blockIdx.x;                 // 0..383: one row
    const int arr = bx >> 7;
    const int row = bx & 127;

    const float* xp = (arr == 0) ? x1 : ((arr == 1) ? x2 : x3);
    const float* xr = xp + (size_t)row * N_CONV;

    const int t = threadIdx.x;

    // ---- Prologue: issue gmem loads FIRST, then compute all twiddles in
    // the LDG latency shadow, then store packed input to smem. ----
    const float4 v0 = ((const float4*)xr)[2 * t];
    const float4 v1 = ((const float4*)xr)[2 * t + 1];

    // Cached twiddles (same registers reused by fwd, inv, epilogue).
    float2 wa1, wa2, wa3;   // stage 512: pos = t
    float2 wb1, wb2, wb3;   // stage 128: pos = t & 31
    float2 wc1, wc2, wc3;   // stage  32: pos = t & 7
    tw3((float)t         * (6.283185307179586f / 512.0f), wa1, wa2, wa3);
    tw3((float)(t & 31)  * (6.283185307179586f / 128.0f), wb1, wb2, wb3);
    tw3((float)(t & 7)   * (6.283185307179586f /  32.0f), wc1, wc2, wc3);
    // Stage 8: pos = t & 1 -> constants.
    const int p8 = t & 1;
    const float2 wd1 = p8 ? make_float2( SQH, -SQH) : make_float2(1.f, 0.f);
    const float2 wd2 = p8 ? make_float2( 0.f, -1.f) : make_float2(1.f, 0.f);
    const float2 wd3 = p8 ? make_float2(-SQH, -SQH) : make_float2(1.f, 0.f);
    // Middle w's: k0 = 2t, k1 = 2t+1; th = k * pi/512.
    const float thm0 = (float)(2 * t)     * 0.006135923151542565f;
    const float thm1 = (float)(2 * t + 1) * 0.006135923151542565f;
    const float2 wm0 = make_float2(fcos(thm0), -fsin(thm0));
    const float2 wm1 = make_float2(fcos(thm1), -fsin(thm1));

    {
        const int b = 4 * t;
        X[P2(b)]     = make_float2(v0.x, v0.y);
        X[P2(b + 1)] = make_float2(v0.z, v0.w);
        X[P2(b + 2)] = make_float2(v1.x, v1.y);
        X[P2(b + 3)] = make_float2(v1.z, v1.w);
    }
    __syncthreads();

    // Forward FFT-512.
    fwd_stage<512>(X, t, wa1, wa2, wa3); __syncthreads();
    fwd_stage<128>(X, t, wb1, wb2, wb3); __syncwarp();
    fwd_stage< 32>(X, t, wc1, wc2, wc3); __syncwarp();
    fwd_stage<  8>(X, t, wd1, wd2, wd3); __syncwarp();
    r2_stage(X, t);
    __syncthreads();   // middle reads scattered global positions

    // Middle: rfft combine + square + inverse-pack, pairwise in-place.
    middle_unit(X, 2 * t,     wm0);
    middle_unit(X, 2 * t + 1, wm1);
    if (t == 0) {
        // k = 256: th = pi/2 -> w = (0, -1) exactly.
        middle_unit(X, 256, make_float2(0.f, -1.f));
    }
    __syncthreads();

    // Inverse: exact unwind (same twiddle registers -> bit-identical).
    r2_stage(X, t);                      __syncwarp();
    inv_stage<  8>(X, t, wd1, wd2, wd3); __syncwarp();
    inv_stage< 32>(X, t, wc1, wc2, wc3); __syncwarp();
    inv_stage<128>(X, t, wb1, wb2, wb3); __syncthreads();

    // Final inverse stage L=512 fused with epilogue de-pack to gmem.
    // (normalization folded into the middle; stage-512 twiddles reused)
    {
        const int i0 = P2(t), i1 = P2(t + 128), i2 = P2(t + 256), i3 = P2(t + 384);

        const float2 a0 = X[i0];
        const float2 a1 = cmulc(X[i1], wa1);
        const float2 a2 = cmulc(X[i2], wa2);
        const float2 a3 = cmulc(X[i3], wa3);

        const float2 t0 = cadd(a0, a2);
        const float2 t1 = csub(a0, a2);
        const float2 t2 = cadd(a1, a3);
        const float2 t3 = csub(a1, a3);

        float2* orow = (float2*)(out + (size_t)arr * 128 * N_CONV
                                     + (size_t)row * N_CONV);
        // v[n] at n = t + 128m -> y[2n] = Re, y[2n+1] = Im.
        orow[t]       = cadd(t0, t2);
        orow[t + 128] = addmuli(t1, t3);
        orow[t + 256] = csub(t0, t2);
        orow[t + 384] = submuli(t1, t3);
    }
}

extern "C" void kernel_launch(void* const* d_in, const int* in_sizes, int n_in,
                              void* d_out, int out_size)
{
    const float* x1 = (const float*)d_in[0];
    const float* x2 = (const float*)d_in[1];
    const float* x3 = (const float*)d_in[2];
    float* out = (float*)d_out;

    mcf_r17_kernel<<<384, THREADS>>>(x1, x2, x3, out);
}